// round 2
// baseline (speedup 1.0000x reference)
#include <cuda_runtime.h>
#include <math.h>

#define BB 8
#define TT 2048
#define HH 1024
#define G3 3072
#define NCTA 128
#define NTHR 256

// ---------------- scratch (no allocations allowed -> device globals) -------
__device__ float g_xproj[(size_t)BB * TT * G3];   // [B*T, 3H], row = b*T + t
__device__ float g_h[2][BB * HH];                 // double-buffered hidden state
__device__ unsigned int g_flags[NCTA];
__device__ unsigned int g_gen;

__device__ __forceinline__ void st_release_gpu(unsigned int* p, unsigned int v) {
    asm volatile("st.release.gpu.u32 [%0], %1;" :: "l"(p), "r"(v) : "memory");
}
__device__ __forceinline__ unsigned int ld_acquire_gpu(const unsigned int* p) {
    unsigned int v;
    asm volatile("ld.acquire.gpu.u32 %0, [%1];" : "=r"(v) : "l"(p) : "memory");
    return v;
}

// ---------------- init: zero state + barrier bookkeeping --------------------
__global__ void gru_init_kernel() {
    int tid = blockIdx.x * blockDim.x + threadIdx.x;
    if (tid < BB * HH) g_h[0][tid] = 0.0f;
    if (tid < NCTA) g_flags[tid] = 0u;
    if (tid == 0) g_gen = 0u;
}

// ---------------- kernel A: x_proj = x @ W_ih^T + b_ih ----------------------
// M = B*T = 16384, N = 3H = 3072, K = H = 1024. 64x64x16 tile, 4x4 microtile.
#define BM 64
#define BN 64
#define BKK 16
#define SSTR 68   // padded smem row stride (floats): 16B-aligned, conflict-free

__global__ void __launch_bounds__(256) xproj_gemm_kernel(
    const float* __restrict__ x,     // [B*T, H]
    const float* __restrict__ Wih,   // [3H, H]
    const float* __restrict__ bih)   // [3H]
{
    __shared__ float As[BKK * SSTR];
    __shared__ float Bs[BKK * SSTR];

    const int tid = threadIdx.x;
    const int m0 = blockIdx.y * BM;
    const int n0 = blockIdx.x * BN;
    const int tx = tid & 15;        // 0..15 (N direction)
    const int ty = tid >> 4;        // 0..15 (M direction)

    const int ldRow = tid >> 2;     // 0..63
    const int ldCol = (tid & 3) * 4;

    const float* aPtr = x   + (size_t)(m0 + ldRow) * HH + ldCol;
    const float* bPtr = Wih + (size_t)(n0 + ldRow) * HH + ldCol;

    float acc[4][4];
#pragma unroll
    for (int i = 0; i < 4; ++i)
#pragma unroll
        for (int j = 0; j < 4; ++j) acc[i][j] = 0.0f;

    for (int k0 = 0; k0 < HH; k0 += BKK) {
        float4 av = *(const float4*)(aPtr + k0);
        float4 bv = *(const float4*)(bPtr + k0);
        As[(ldCol + 0) * SSTR + ldRow] = av.x;
        As[(ldCol + 1) * SSTR + ldRow] = av.y;
        As[(ldCol + 2) * SSTR + ldRow] = av.z;
        As[(ldCol + 3) * SSTR + ldRow] = av.w;
        Bs[(ldCol + 0) * SSTR + ldRow] = bv.x;
        Bs[(ldCol + 1) * SSTR + ldRow] = bv.y;
        Bs[(ldCol + 2) * SSTR + ldRow] = bv.z;
        Bs[(ldCol + 3) * SSTR + ldRow] = bv.w;
        __syncthreads();

#pragma unroll
        for (int kk = 0; kk < BKK; ++kk) {
            float4 a = *(const float4*)(As + kk * SSTR + ty * 4);
            float4 b = *(const float4*)(Bs + kk * SSTR + tx * 4);
            float ar[4] = {a.x, a.y, a.z, a.w};
            float br[4] = {b.x, b.y, b.z, b.w};
#pragma unroll
            for (int i = 0; i < 4; ++i)
#pragma unroll
                for (int j = 0; j < 4; ++j)
                    acc[i][j] = fmaf(ar[i], br[j], acc[i][j]);
        }
        __syncthreads();
    }

    float4 bias = *(const float4*)(bih + n0 + tx * 4);
#pragma unroll
    for (int i = 0; i < 4; ++i) {
        float4 o;
        o.x = acc[i][0] + bias.x;
        o.y = acc[i][1] + bias.y;
        o.z = acc[i][2] + bias.z;
        o.w = acc[i][3] + bias.w;
        *(float4*)(g_xproj + (size_t)(m0 + ty * 4 + i) * G3 + n0 + tx * 4) = o;
    }
}

// ---------------- kernel B: persistent recurrence ---------------------------
// 128 CTAs x 256 threads. CTA c owns hidden columns [8c, 8c+8); warp j owns
// column col = 8c + j; its 3 W_hh rows (r,z,n) live in SMEM for the whole run.
// Lane q covers k = i*32 + q  ->  every SMEM access lands on bank q (stride
// multiples of 32 floats), conflict-free by construction.

__device__ __forceinline__ float sigmoidf_(float v) {
    return 1.0f / (1.0f + expf(-v));
}

__global__ void __launch_bounds__(NTHR, 1) gru_recurrent_kernel(
    const float* __restrict__ Whh,   // [3H, H]
    const float* __restrict__ bhh,   // [3H]
    float* __restrict__ out)         // [B, T, H]
{
    extern __shared__ float smem[];
    float* sW = smem;                 // [24][1024]
    float* sh = smem + 24 * HH;       // [8][1024]  (full h, b-major)

    const int tid  = threadIdx.x;
    const int cta  = blockIdx.x;
    const int warp = tid >> 5;
    const int lane = tid & 31;
    const int col  = cta * 8 + warp;  // global hidden column of this warp

    // Load W_hh slice: local row r = j*3 + g  <->  global row g*H + (8*cta + j)
    for (int idx = tid; idx < 24 * (HH / 4); idx += NTHR) {
        int r  = idx / (HH / 4);
        int k4 = idx % (HH / 4);
        int j = r / 3, g = r % 3;
        int grow = g * HH + cta * 8 + j;
        float4 v = ((const float4*)(Whh + (size_t)grow * HH))[k4];
        ((float4*)(sW + r * HH))[k4] = v;
    }
    const float bh_r = bhh[col];
    const float bh_z = bhh[HH + col];
    const float bh_n = bhh[2 * HH + col];
    __syncthreads();

    const float* w0p = sW + (warp * 3 + 0) * HH;
    const float* w1p = sW + (warp * 3 + 1) * HH;
    const float* w2p = sW + (warp * 3 + 2) * HH;

    for (int t = 0; t < TT; ++t) {
        const float* hin  = g_h[t & 1];
        float*       hout = g_h[(t + 1) & 1];

        // Prefetch this step's x_proj gates (lanes 0..7 <-> batch b)
        float xr = 0.f, xz = 0.f, xn = 0.f;
        if (lane < 8) {
            const float* p = g_xproj + ((size_t)lane * TT + t) * G3;
            xr = __ldg(p + col);
            xz = __ldg(p + HH + col);
            xn = __ldg(p + 2 * HH + col);
        }

        // Stage full h into SMEM (L2-coherent loads; L1 would be stale)
#pragma unroll
        for (int i = 0; i < 8; ++i) {
            int idx4 = tid + i * NTHR;  // 2048 float4 total
            float4 v = __ldcg(((const float4*)hin) + idx4);
            ((float4*)sh)[idx4] = v;
        }
        __syncthreads();

        // Dot products: acc[gate][batch], K split over 32 lanes
        float acc[3][8];
#pragma unroll
        for (int g = 0; g < 3; ++g)
#pragma unroll
            for (int b = 0; b < 8; ++b) acc[g][b] = 0.0f;

#pragma unroll 8
        for (int i = 0; i < 32; ++i) {
            int k = i * 32 + lane;
            float w0 = w0p[k];
            float w1 = w1p[k];
            float w2 = w2p[k];
#pragma unroll
            for (int b = 0; b < 8; ++b) {
                float hv = sh[b * HH + k];
                acc[0][b] = fmaf(w0, hv, acc[0][b]);
                acc[1][b] = fmaf(w1, hv, acc[1][b]);
                acc[2][b] = fmaf(w2, hv, acc[2][b]);
            }
        }

        // Butterfly reduce across the warp
#pragma unroll
        for (int off = 16; off > 0; off >>= 1) {
#pragma unroll
            for (int g = 0; g < 3; ++g)
#pragma unroll
                for (int b = 0; b < 8; ++b)
                    acc[g][b] += __shfl_xor_sync(0xffffffffu, acc[g][b], off);
        }

        // Lanes 0..7 finalize one batch element each.
        // NOTE: b_hh_n goes INSIDE the r* term: n = tanh(xn + r*(Whh_n.h + bhh_n))
        if (lane < 8) {
            int b = lane;
            float hprev = sh[b * HH + col];
            float r = sigmoidf_(xr + bh_r + acc[0][b]);
            float z = sigmoidf_(xz + bh_z + acc[1][b]);
            float n = tanhf(xn + r * (acc[2][b] + bh_n));
            float hnew = (1.0f - z) * n + z * hprev;
            out[((size_t)b * TT + t) * HH + col] = hnew;
            __stcg(&hout[b * HH + col], hnew);
        }

        // ---- grid barrier (flag array + generation counter, release/acquire) ----
        __syncthreads();
        if (tid == 0) {
            st_release_gpu(&g_flags[cta], (unsigned)(t + 1));
        }
        if (cta == 0) {
            if (tid < NCTA) {
                while (ld_acquire_gpu(&g_flags[tid]) < (unsigned)(t + 1)) { }
            }
            __syncthreads();
            if (tid == 0) {
                st_release_gpu(&g_gen, (unsigned)(t + 1));
            }
        }
        if (tid == 0) {
            while (ld_acquire_gpu(&g_gen) < (unsigned)(t + 1)) { }
        }
        __syncthreads();
    }
}

// ---------------- launcher ---------------------------------------------------
extern "C" void kernel_launch(void* const* d_in, const int* in_sizes, int n_in,
                              void* d_out, int out_size) {
    const float* x   = (const float*)d_in[0];
    const float* Wih = (const float*)d_in[1];
    const float* bih = (const float*)d_in[2];
    const float* Whh = (const float*)d_in[3];
    const float* bhh = (const float*)d_in[4];
    float* out = (float*)d_out;

    (void)in_sizes; (void)n_in; (void)out_size;

    // 128KB dynamic smem for the persistent kernel (idempotent)
    static const int kSmem = (24 * HH + BB * HH) * (int)sizeof(float);
    cudaFuncSetAttribute(gru_recurrent_kernel,
                         cudaFuncAttributeMaxDynamicSharedMemorySize, kSmem);

    gru_init_kernel<<<32, 256>>>();

    dim3 g1(G3 / BN, (BB * TT) / BM);   // 48 x 256
    xproj_gemm_kernel<<<g1, 256>>>(x, Wih, bih);

    gru_recurrent_kernel<<<NCTA, NTHR, kSmem>>>(Whh, bhh, out);
}

// round 3
// speedup vs baseline: 1.2662x; 1.2662x over previous
#include <cuda_runtime.h>
#include <math.h>

#define BB 8
#define TT 2048
#define HH 1024
#define G3 3072
#define NCTA 128
#define NTHR 256
#define FPAD 32   // one flag per 128B line

typedef unsigned long long u64;

// ---------------- persistent scratch (device globals; zero-initialized) -----
__device__ float g_xproj[(size_t)BB * TT * G3];   // [B*T, 3H], row = b*T + t
__device__ float g_h[2][BB * HH];                 // double-buffered hidden state
__device__ unsigned int g_flags[NCTA * FPAD];     // grid-barrier flags (monotonic)

__device__ __forceinline__ void st_release_gpu(unsigned int* p, unsigned int v) {
    asm volatile("st.release.gpu.u32 [%0], %1;" :: "l"(p), "r"(v) : "memory");
}
__device__ __forceinline__ unsigned int ld_acquire_gpu(const unsigned int* p) {
    unsigned int v;
    asm volatile("ld.acquire.gpu.u32 %0, [%1];" : "=r"(v) : "l"(p) : "memory");
    return v;
}
// packed fp32x2 FMA (Blackwell): d = a*b + c elementwise on (lo,hi)
__device__ __forceinline__ u64 fma2(u64 a, u64 b, u64 c) {
    u64 d;
    asm("fma.rn.f32x2 %0, %1, %2, %3;" : "=l"(d) : "l"(a), "l"(b), "l"(c));
    return d;
}
__device__ __forceinline__ float fold2(u64 v) {
    return __uint_as_float((unsigned)v) + __uint_as_float((unsigned)(v >> 32));
}
__device__ __forceinline__ float sigmoidf_(float v) {
    return 1.0f / (1.0f + expf(-v));
}

// ---------------- kernel A: x_proj = x @ W_ih^T + b_ih ----------------------
// M=16384, N=3072, K=1024. Tile 64(M) x 128(N) x 16(K); microtile 4x8.
// Even/odd-K packed FFMA2: acc halves hold even-k / odd-k partial sums.
#define BM 64
#define BN 128
#define BKK 16
#define APAD 18
#define BPAD 18

__global__ void __launch_bounds__(256, 2) xproj_gemm_kernel(
    const float* __restrict__ x,     // [B*T, H]
    const float* __restrict__ Wih,   // [3H, H]
    const float* __restrict__ bih)   // [3H]
{
    __shared__ float As[BM * APAD];   // [64][18]  row-major (k contiguous)
    __shared__ float Bs[BN * BPAD];   // [128][18]

    const int tid = threadIdx.x;
    const int m0 = blockIdx.y * BM;
    const int n0 = blockIdx.x * BN;
    const int tx = tid & 15;          // N dir: cols tx*8 .. tx*8+7
    const int ty = tid >> 4;          // M dir: rows ty*4 .. ty*4+3

    const int ldRow = tid >> 2;       // 0..63
    const int ldCol = (tid & 3) * 4;  // 0,4,8,12

    const float* aPtr  = x   + (size_t)(m0 + ldRow) * HH + ldCol;
    const float* bPtr0 = Wih + (size_t)(n0 + ldRow) * HH + ldCol;
    const float* bPtr1 = Wih + (size_t)(n0 + ldRow + 64) * HH + ldCol;

    u64 acc[4][8];
#pragma unroll
    for (int i = 0; i < 4; ++i)
#pragma unroll
        for (int u = 0; u < 8; ++u) acc[i][u] = 0ull;

    for (int k0 = 0; k0 < HH; k0 += BKK) {
        float4 av  = *(const float4*)(aPtr  + k0);
        float4 bv0 = *(const float4*)(bPtr0 + k0);
        float4 bv1 = *(const float4*)(bPtr1 + k0);

        *(float2*)&As[ldRow * APAD + ldCol + 0] = make_float2(av.x, av.y);
        *(float2*)&As[ldRow * APAD + ldCol + 2] = make_float2(av.z, av.w);
        *(float2*)&Bs[ldRow * BPAD + ldCol + 0] = make_float2(bv0.x, bv0.y);
        *(float2*)&Bs[ldRow * BPAD + ldCol + 2] = make_float2(bv0.z, bv0.w);
        *(float2*)&Bs[(ldRow + 64) * BPAD + ldCol + 0] = make_float2(bv1.x, bv1.y);
        *(float2*)&Bs[(ldRow + 64) * BPAD + ldCol + 2] = make_float2(bv1.z, bv1.w);
        __syncthreads();

#pragma unroll
        for (int kk2 = 0; kk2 < BKK / 2; ++kk2) {
            u64 a2[4];
#pragma unroll
            for (int i = 0; i < 4; ++i)
                a2[i] = *(const u64*)&As[(ty * 4 + i) * APAD + kk2 * 2];
            u64 b2[8];
#pragma unroll
            for (int u = 0; u < 8; ++u)
                b2[u] = *(const u64*)&Bs[(tx * 8 + u) * BPAD + kk2 * 2];
#pragma unroll
            for (int i = 0; i < 4; ++i)
#pragma unroll
                for (int u = 0; u < 8; ++u)
                    acc[i][u] = fma2(a2[i], b2[u], acc[i][u]);
        }
        __syncthreads();
    }

    float4 bia0 = *(const float4*)(bih + n0 + tx * 8);
    float4 bia1 = *(const float4*)(bih + n0 + tx * 8 + 4);
#pragma unroll
    for (int i = 0; i < 4; ++i) {
        float v[8];
#pragma unroll
        for (int u = 0; u < 8; ++u) v[u] = fold2(acc[i][u]);
        float4 o0, o1;
        o0.x = v[0] + bia0.x; o0.y = v[1] + bia0.y;
        o0.z = v[2] + bia0.z; o0.w = v[3] + bia0.w;
        o1.x = v[4] + bia1.x; o1.y = v[5] + bia1.y;
        o1.z = v[6] + bia1.z; o1.w = v[7] + bia1.w;
        float* orow = g_xproj + (size_t)(m0 + ty * 4 + i) * G3 + n0 + tx * 8;
        *(float4*)(orow)     = o0;
        *(float4*)(orow + 4) = o1;
    }
}

// ---------------- kernel B: persistent recurrence ---------------------------
// 128 CTAs x 256 threads (1 CTA/SM). CTA c owns hidden cols [8c, 8c+8); warp j
// owns col 8c+j; its 3 W_hh rows live in SMEM. Even/odd-K FFMA2: lane handles
// k-pair k2 = i*64 + lane*2, contiguous float2 loads (conflict-free LDS.64).
__global__ void __launch_bounds__(NTHR, 1) gru_recurrent_kernel(
    const float* __restrict__ Whh,   // [3H, H]
    const float* __restrict__ bhh,   // [3H]
    float* __restrict__ out)         // [B, T, H]
{
    extern __shared__ float smem[];
    float* sW = smem;                 // [24][1024]
    float* sh = smem + 24 * HH;       // [8][1024]  (b-major)

    const int tid  = threadIdx.x;
    const int cta  = blockIdx.x;
    const int warp = tid >> 5;
    const int lane = tid & 31;
    const int col  = cta * 8 + warp;

    // Load W_hh slice: local row r = j*3 + g  <->  global row g*H + (8*cta + j)
    for (int idx = tid; idx < 24 * (HH / 4); idx += NTHR) {
        int r  = idx / (HH / 4);
        int k4 = idx % (HH / 4);
        int j = r / 3, g = r % 3;
        int grow = g * HH + cta * 8 + j;
        float4 v = ((const float4*)(Whh + (size_t)grow * HH))[k4];
        ((float4*)(sW + r * HH))[k4] = v;
    }
    const float bh_r = bhh[col];
    const float bh_z = bhh[HH + col];
    const float bh_n = bhh[2 * HH + col];
    __syncthreads();

    const float* w0p = sW + (warp * 3 + 0) * HH;
    const float* w1p = sW + (warp * 3 + 1) * HH;
    const float* w2p = sW + (warp * 3 + 2) * HH;

    // Barrier base: all flags are equal at kernel entry (monotonic protocol).
    const unsigned v0 = ld_acquire_gpu(&g_flags[cta * FPAD]);

    for (int t = 0; t < TT; ++t) {
        // Prefetch this step's x_proj gates (lanes 0..7 <-> batch b)
        float xr = 0.f, xz = 0.f, xn = 0.f;
        if (lane < 8) {
            const float* p = g_xproj + ((size_t)lane * TT + t) * G3;
            xr = __ldg(p + col);
            xz = __ldg(p + HH + col);
            xn = __ldg(p + 2 * HH + col);
        }

        // Stage h into SMEM (t=0: h0 = 0, no global read needed)
        if (t == 0) {
            float4 z4 = make_float4(0.f, 0.f, 0.f, 0.f);
#pragma unroll
            for (int i = 0; i < 8; ++i)
                ((float4*)sh)[tid + i * NTHR] = z4;
        } else {
            const float* hin = g_h[t & 1];
#pragma unroll
            for (int i = 0; i < 8; ++i) {
                int idx4 = tid + i * NTHR;
                ((float4*)sh)[idx4] = __ldcg(((const float4*)hin) + idx4);
            }
        }
        __syncthreads();

        // Dot products: acc[gate][batch] as f32x2 (even/odd-k halves)
        u64 acc[3][8];
#pragma unroll
        for (int g = 0; g < 3; ++g)
#pragma unroll
            for (int b = 0; b < 8; ++b) acc[g][b] = 0ull;

#pragma unroll 4
        for (int i = 0; i < 16; ++i) {
            int k2 = i * 64 + lane * 2;
            u64 w0 = *(const u64*)(w0p + k2);
            u64 w1 = *(const u64*)(w1p + k2);
            u64 w2 = *(const u64*)(w2p + k2);
#pragma unroll
            for (int b = 0; b < 8; ++b) {
                u64 hb = *(const u64*)(sh + b * HH + k2);
                acc[0][b] = fma2(w0, hb, acc[0][b]);
                acc[1][b] = fma2(w1, hb, acc[1][b]);
                acc[2][b] = fma2(w2, hb, acc[2][b]);
            }
        }

        // Fold even/odd halves, then butterfly-reduce across the warp
        float s[3][8];
#pragma unroll
        for (int g = 0; g < 3; ++g)
#pragma unroll
            for (int b = 0; b < 8; ++b) s[g][b] = fold2(acc[g][b]);

#pragma unroll
        for (int off = 16; off > 0; off >>= 1) {
#pragma unroll
            for (int g = 0; g < 3; ++g)
#pragma unroll
                for (int b = 0; b < 8; ++b)
                    s[g][b] += __shfl_xor_sync(0xffffffffu, s[g][b], off);
        }

        // Lanes 0..7 finalize one batch each. b_hh_n sits INSIDE the r* term.
        if (lane < 8) {
            int b = lane;
            float hprev = sh[b * HH + col];
            float r = sigmoidf_(xr + bh_r + s[0][b]);
            float z = sigmoidf_(xz + bh_z + s[1][b]);
            float n = tanhf(xn + r * (s[2][b] + bh_n));
            float hnew = (1.0f - z) * n + z * hprev;
            out[((size_t)b * TT + t) * HH + col] = hnew;
            __stcg(&g_h[(t + 1) & 1][b * HH + col], hnew);
        }

        // ---- distributed single-phase grid barrier ----
        __syncthreads();
        if (tid == 0) st_release_gpu(&g_flags[cta * FPAD], v0 + (unsigned)(t + 1));
        if (tid < NCTA) {
            while (ld_acquire_gpu(&g_flags[tid * FPAD]) - v0 < (unsigned)(t + 1)) { }
        }
        __syncthreads();
    }
    // flags end equal at v0 + TT for all CTAs -> valid base for next replay
}

// ---------------- launcher ---------------------------------------------------
extern "C" void kernel_launch(void* const* d_in, const int* in_sizes, int n_in,
                              void* d_out, int out_size) {
    const float* x   = (const float*)d_in[0];
    const float* Wih = (const float*)d_in[1];
    const float* bih = (const float*)d_in[2];
    const float* Whh = (const float*)d_in[3];
    const float* bhh = (const float*)d_in[4];
    float* out = (float*)d_out;

    (void)in_sizes; (void)n_in; (void)out_size;

    const int kSmem = (24 * HH + BB * HH) * (int)sizeof(float);  // 128KB
    cudaFuncSetAttribute(gru_recurrent_kernel,
                         cudaFuncAttributeMaxDynamicSharedMemorySize, kSmem);

    dim3 g1(G3 / BN, (BB * TT) / BM);   // 24 x 256
    xproj_gemm_kernel<<<g1, 256>>>(x, Wih, bih);

    gru_recurrent_kernel<<<NCTA, NTHR, kSmem>>>(Whh, bhh, out);
}